// round 17
// baseline (speedup 1.0000x reference)
#include <cuda_runtime.h>
#include <cstdint>
#include <cstddef>

constexpr int B_  = 4;
constexpr int DE  = 128;
constexpr int DO  = 512;
constexpr int K_  = 12960;   // 8*30*54 = 405*32
constexpr int Q_  = 1620;    // 30*54

constexpr int QT   = 96;
constexpr int NQT  = 17;          // ceil(1620/96)
constexpr int QPAD = NQT * QT;    // 1632
constexpr int KT   = 128;
constexpr int NKT  = 102;         // ceil(12960/128)

constexpr int MEM_ELEMS = B_ * DO * Q_;
constexpr float SCALE = 0.088388347648318447f;  // 1/sqrt(128)

// scratch: static device globals (no runtime allocation)
// g_e padded: K3's cp.async tail chunks may read up to 48B past the last row.
__device__ float g_e[(size_t)B_ * K_ * Q_ + 64];
__device__ float g_part[(size_t)B_ * NKT * QPAD];
__device__ float g_inv[(size_t)B_ * QPAD];

__device__ __forceinline__ uint32_t f2tf(float x) {
    uint32_t u;
    asm("cvt.rna.tf32.f32 %0, %1;" : "=r"(u) : "f"(x));
    return u;
}

// D(16x8) += A(16x8 row) * B(8x8 col), tf32 in, fp32 accum
__device__ __forceinline__ void mma8(float* c, const uint32_t* a, const uint32_t* b) {
    asm volatile(
        "mma.sync.aligned.m16n8k8.row.col.f32.tf32.tf32.f32 "
        "{%0,%1,%2,%3}, {%4,%5,%6,%7}, {%8,%9}, {%0,%1,%2,%3};\n"
        : "+f"(c[0]), "+f"(c[1]), "+f"(c[2]), "+f"(c[3])
        : "r"(a[0]), "r"(a[1]), "r"(a[2]), "r"(a[3]),
          "r"(b[0]), "r"(b[1]));
}

__device__ __forceinline__ uint32_t s2u(const void* p) {
    return (uint32_t)__cvta_generic_to_shared(p);
}
__device__ __forceinline__ void cpa16(uint32_t dst, const float* src) {
    asm volatile("cp.async.cg.shared.global [%0], [%1], 16;\n" :: "r"(dst), "l"(src));
}
__device__ __forceinline__ void cpcommit() {
    asm volatile("cp.async.commit_group;\n");
}

// ===========================================================================
// K1 (R16-frozen): e = exp(S/sqrt(DE)); S = m_in^T q_in. Partial sums.
// cp.async double-buffered; raw fp32 tiles; cvt.rna on fragment loads.
// ===========================================================================
constexpr int K1A = 32 * 136;   // floats per A buffer
constexpr int K1B = 32 * 104;   // floats per B buffer
constexpr int K1SMEMF = 2 * K1A + 2 * K1B + 384;   // 15744 floats = 62976 B

__global__ __launch_bounds__(256, 2)
void k1_scores(const float* __restrict__ m_in, const float* __restrict__ q_in)
{
    extern __shared__ float smf[];
    float* Af = smf;                    // 2 buffers
    float* Bf = smf + 2 * K1A;          // 2 buffers
    float* cs = smf + 2 * K1A + 2 * K1B;

    const int tid  = threadIdx.x;
    const int wid  = tid >> 5;
    const int lane = tid & 31;
    const int g    = lane >> 2;
    const int tg   = lane & 3;
    const int wm   = wid & 3;
    const int wn   = wid >> 2;

    const int kt = blockIdx.x;
    const int qt = blockIdx.y;
    const int b  = blockIdx.z;
    const int k0 = kt * KT;
    const int q0 = qt * QT;

    const float* mi = m_in + (size_t)b * DE * K_;
    const float* qi = q_in + (size_t)b * DE * Q_;

    uint32_t aoff[4], asmo[4]; bool aval[4];
#pragma unroll
    for (int it = 0; it < 4; ++it) {
        int i   = tid + it * 256;        // 1024 chunks: [dd 32][kkc 32]
        int dd  = i >> 5;
        int kk  = (i & 31) * 4;
        aval[it] = (k0 + kk) < K_;
        aoff[it] = (uint32_t)(dd * K_ + k0 + kk);
        asmo[it] = (uint32_t)(dd * 136 + kk);
    }
    uint32_t boff[3], bsmo[3]; bool bval[3];
#pragma unroll
    for (int it = 0; it < 3; ++it) {
        int i   = tid + it * 256;        // 768 chunks: [dd 32][qc 24]
        int dd  = i / 24;
        int q   = (i - dd * 24) * 4;
        bval[it] = (q0 + q) < Q_;
        boff[it] = (uint32_t)(dd * Q_ + q0 + q);
        bsmo[it] = (uint32_t)(dd * 104 + q);
    }

    const float4 z4 = {0.f, 0.f, 0.f, 0.f};
#pragma unroll
    for (int it = 0; it < 4; ++it)
        if (!aval[it]) {
            *reinterpret_cast<float4*>(Af + asmo[it])        = z4;
            *reinterpret_cast<float4*>(Af + K1A + asmo[it])  = z4;
        }
#pragma unroll
    for (int it = 0; it < 3; ++it)
        if (!bval[it]) {
            *reinterpret_cast<float4*>(Bf + bsmo[it])        = z4;
            *reinterpret_cast<float4*>(Bf + K1B + bsmo[it])  = z4;
        }

    const uint32_t Abase = s2u(Af);
    const uint32_t Bbase = s2u(Bf);

    float acc[2][6][4];
#pragma unroll
    for (int mt = 0; mt < 2; ++mt)
#pragma unroll
        for (int nt = 0; nt < 6; ++nt)
#pragma unroll
            for (int j = 0; j < 4; ++j) acc[mt][nt][j] = 0.f;

#pragma unroll
    for (int it = 0; it < 4; ++it) {
        if (aval[it]) cpa16(Abase + asmo[it] * 4, mi + aoff[it]);
        aoff[it] += 32u * K_;
    }
#pragma unroll
    for (int it = 0; it < 3; ++it) {
        if (bval[it]) cpa16(Bbase + bsmo[it] * 4, qi + boff[it]);
        boff[it] += 32u * Q_;
    }
    cpcommit();

#pragma unroll
    for (int dc = 0; dc < 4; ++dc) {
        if (dc < 3) {
            const uint32_t sa = Abase + ((dc + 1) & 1) * (K1A * 4);
            const uint32_t sb = Bbase + ((dc + 1) & 1) * (K1B * 4);
#pragma unroll
            for (int it = 0; it < 4; ++it) {
                if (aval[it]) cpa16(sa + asmo[it] * 4, mi + aoff[it]);
                aoff[it] += 32u * K_;
            }
#pragma unroll
            for (int it = 0; it < 3; ++it) {
                if (bval[it]) cpa16(sb + bsmo[it] * 4, qi + boff[it]);
                boff[it] += 32u * Q_;
            }
            cpcommit();
            asm volatile("cp.async.wait_group 1;\n" ::: "memory");
        } else {
            asm volatile("cp.async.wait_group 0;\n" ::: "memory");
        }
        __syncthreads();

        const float* A  = Af + (dc & 1) * K1A;
        const float* Bv = Bf + (dc & 1) * K1B;

#pragma unroll
        for (int ks = 0; ks < 4; ++ks) {
            const int c = ks * 8 + tg;
            uint32_t af[2][4];
#pragma unroll
            for (int mt = 0; mt < 2; ++mt) {
                int r = wm * 32 + mt * 16 + g;
                af[mt][0] = f2tf(A[c * 136 + r]);
                af[mt][1] = f2tf(A[c * 136 + r + 8]);
                af[mt][2] = f2tf(A[(c + 4) * 136 + r]);
                af[mt][3] = f2tf(A[(c + 4) * 136 + r + 8]);
            }
#pragma unroll
            for (int nt = 0; nt < 6; ++nt) {
                int n = wn * 48 + nt * 8 + g;
                uint32_t bf[2] = { f2tf(Bv[c * 104 + n]), f2tf(Bv[(c + 4) * 104 + n]) };
                mma8(acc[0][nt], af[0], bf);
                mma8(acc[1][nt], af[1], bf);
            }
        }
        __syncthreads();
    }

    float ls[6][2];
#pragma unroll
    for (int nt = 0; nt < 6; ++nt) { ls[nt][0] = 0.f; ls[nt][1] = 0.f; }

#pragma unroll
    for (int mt = 0; mt < 2; ++mt)
#pragma unroll
        for (int nt = 0; nt < 6; ++nt)
#pragma unroll
            for (int j = 0; j < 4; ++j) {
                int r  = wm * 32 + mt * 16 + ((j & 2) ? (g + 8) : g);
                int kg = k0 + r;
                float e = (kg < K_) ? __expf(acc[mt][nt][j] * SCALE) : 0.f;
                acc[mt][nt][j] = e;
                ls[nt][j & 1] += e;
            }

#pragma unroll
    for (int nt = 0; nt < 6; ++nt)
#pragma unroll
        for (int p = 0; p < 2; ++p) {
            float v = ls[nt][p];
            v += __shfl_xor_sync(0xffffffffu, v, 4);
            v += __shfl_xor_sync(0xffffffffu, v, 8);
            v += __shfl_xor_sync(0xffffffffu, v, 16);
            if (g == 0) cs[wm * 96 + wn * 48 + nt * 8 + tg * 2 + p] = v;
        }
    __syncthreads();

    if (tid < 96) {
        float s = cs[tid] + cs[96 + tid] + cs[192 + tid] + cs[288 + tid];
        g_part[((size_t)b * NKT + kt) * QPAD + qt * QT + tid] = s;
    }

    float* stg = Af;   // 32 x (stride 100)
#pragma unroll 1
    for (int chunk = 0; chunk < 4; ++chunk) {
        __syncthreads();
        if (wm == chunk) {
#pragma unroll
            for (int mt = 0; mt < 2; ++mt)
#pragma unroll
                for (int nt = 0; nt < 6; ++nt)
#pragma unroll
                    for (int j = 0; j < 4; ++j) {
                        int r = mt * 16 + ((j & 2) ? (g + 8) : g);
                        int c = wn * 48 + nt * 8 + tg * 2 + (j & 1);
                        stg[r * 100 + c] = __uint_as_float(f2tf(acc[mt][nt][j]));
                    }
        }
        __syncthreads();
#pragma unroll
        for (int it = 0; it < 3; ++it) {
            int i = tid + it * 256;              // 32 rows x 24 float4
            int r = i / 24, j = i - r * 24;
            int kg = k0 + chunk * 32 + r;
            int qg = q0 + j * 4;
            if (kg < K_ && qg < Q_) {
                float4 v = *reinterpret_cast<const float4*>(stg + r * 100 + j * 4);
                *reinterpret_cast<float4*>(
                    g_e + ((size_t)b * K_ + kg) * Q_ + qg) = v;
            }
        }
    }
}

// ===========================================================================
// K2: g_inv[b,q] = 1 / (exp(const) + sum_kt g_part)
// ===========================================================================
__global__ void k2_inv(const float* __restrict__ cst)
{
    int t = blockIdx.x * blockDim.x + threadIdx.x;
    if (t >= B_ * QPAD) return;
    int b  = t / QPAD;
    int qp = t - b * QPAD;
    float d = expf(cst[0]);
    const float* gp = g_part + (size_t)b * NKT * QPAD + qp;
#pragma unroll 4
    for (int kt = 0; kt < NKT; ++kt) d += gp[(size_t)kt * QPAD];
    g_inv[t] = 1.f / d;
}

// ===========================================================================
// K3: U = m_out @ g_e. NEW: block tile M=64 x N=96 (grid 8x17x4), warp map
// 2(m)x4(n), warp tile 32x24, acc 24 regs. __launch_bounds__(256,3) ->
// 3 CTAs/SM = 24 warps (was 16): the regfile cap that froze the 719us
// plateau. Same 2-stage cp.async pipeline; raw m_out with cvt-on-frag-load
// (R16-proven); p duty (kc&7)==dot; k-order per output unchanged.
// ===========================================================================
constexpr int ASTR  = 64 * 36;    // floats per A stage
constexpr int BSTR  = 32 * 104;   // floats per B stage
constexpr int SMEMF = 2 * ASTR + 2 * BSTR + 96;   // 11360 floats = 45440 B

__global__ __launch_bounds__(256, 3)
void k3_out(const float* __restrict__ m_out,
            float* __restrict__ out_mem, float* __restrict__ out_p)
{
    extern __shared__ float sm[];
    float* Ab   = sm;
    float* Bb   = sm + 2 * ASTR;
    float* sinv = sm + 2 * ASTR + 2 * BSTR;

    const int tid  = threadIdx.x;
    const int wid  = tid >> 5;
    const int lane = tid & 31;
    const int g    = lane >> 2;
    const int tg   = lane & 3;
    const int wm   = wid & 1;     // 2 m-warps
    const int wn   = wid >> 1;    // 4 n-warps

    const int dot = blockIdx.x;   // 0..7
    const int qt  = blockIdx.y;   // 0..16
    const int b   = blockIdx.z;
    const int q0  = qt * QT;
    const int do0 = dot * 64;

    if (tid < 96) sinv[tid] = g_inv[(size_t)b * QPAD + q0 + tid];

    // cp.async descriptors: A 512 chunks (2/thread), B 768 chunks (3/thread)
    const float* asrc[2]; uint32_t aoff[2];
#pragma unroll
    for (int it = 0; it < 2; ++it) {
        int i = tid + it * 256;          // A: 64 rows x 32 floats
        int row = i >> 3;
        int kc4 = (i & 7) * 4;
        asrc[it] = m_out + ((size_t)b * DO + do0 + row) * K_ + kc4;
        aoff[it] = (uint32_t)((row * 36 + kc4) * 4);
    }
    const float* bsrc[3]; uint32_t boff[3]; int bkk[3], bqc[3];
#pragma unroll
    for (int it = 0; it < 3; ++it) {
        int i  = tid + it * 256;         // B: 32 rows x 96 floats
        int kk = i / 24;
        int qc = (i - kk * 24) * 4;
        bkk[it] = kk; bqc[it] = qc;
        bsrc[it] = g_e + (size_t)b * K_ * Q_ + (size_t)kk * Q_ + q0 + qc;
        boff[it] = (uint32_t)((kk * 104 + qc) * 4);
    }
    const uint32_t Abase = s2u(Ab);
    const uint32_t Bbase = s2u(Bb);

    float acc[2][3][4];
#pragma unroll
    for (int mt = 0; mt < 2; ++mt)
#pragma unroll
        for (int nt = 0; nt < 3; ++nt)
#pragma unroll
            for (int j = 0; j < 4; ++j) acc[mt][nt][j] = 0.f;

    // prologue: stage kc=0 into buffer 0
#pragma unroll
    for (int it = 0; it < 2; ++it) cpa16(Abase + aoff[it], asrc[it]);
#pragma unroll
    for (int it = 0; it < 3; ++it) cpa16(Bbase + boff[it], bsrc[it]);
    cpcommit();
#pragma unroll
    for (int it = 0; it < 2; ++it) asrc[it] += 32;
#pragma unroll
    for (int it = 0; it < 3; ++it) bsrc[it] += (size_t)32 * Q_;

    float* pout = out_p + (size_t)b * K_ * Q_;

#pragma unroll 1
    for (int kc = 0; kc < 405; ++kc) {
        if (kc < 404) {
            const uint32_t sa = Abase + ((kc + 1) & 1) * (ASTR * 4);
            const uint32_t sb = Bbase + ((kc + 1) & 1) * (BSTR * 4);
#pragma unroll
            for (int it = 0; it < 2; ++it) { cpa16(sa + aoff[it], asrc[it]); asrc[it] += 32; }
#pragma unroll
            for (int it = 0; it < 3; ++it) { cpa16(sb + boff[it], bsrc[it]); bsrc[it] += (size_t)32 * Q_; }
            cpcommit();
            asm volatile("cp.async.wait_group 1;\n" ::: "memory");
        } else {
            asm volatile("cp.async.wait_group 0;\n" ::: "memory");
        }
        __syncthreads();

        const float* A  = Ab + (kc & 1) * ASTR;
        const float* Bv = Bb + (kc & 1) * BSTR;

#pragma unroll
        for (int ks = 0; ks < 4; ++ks) {
            const int c = ks * 8 + tg;
            uint32_t af[2][4];
#pragma unroll
            for (int mt = 0; mt < 2; ++mt) {
                int r = wm * 32 + mt * 16 + g;
                af[mt][0] = f2tf(A[r * 36 + c]);
                af[mt][1] = f2tf(A[(r + 8) * 36 + c]);
                af[mt][2] = f2tf(A[r * 36 + c + 4]);
                af[mt][3] = f2tf(A[(r + 8) * 36 + c + 4]);
            }
#pragma unroll
            for (int nt = 0; nt < 3; ++nt) {
                int n = wn * 24 + nt * 8 + g;
                uint32_t bf[2] = { __float_as_uint(Bv[c * 104 + n]),
                                   __float_as_uint(Bv[(c + 4) * 104 + n]) };
                mma8(acc[0][nt], af[0], bf);
                mma8(acc[1][nt], af[1], bf);
            }
        }

        // p output: normalized e, from the smem tile (1/8 duty cycle)
        if ((kc & 7) == dot) {
            const int k0 = kc * 32;
#pragma unroll
            for (int it = 0; it < 3; ++it) {
                const int kk = bkk[it], qc = bqc[it];
                float4 v = *reinterpret_cast<const float4*>(Bv + kk * 104 + qc);
                float4 w;
                w.x = v.x * sinv[qc];
                w.y = v.y * sinv[qc + 1];
                w.z = v.z * sinv[qc + 2];
                w.w = v.w * sinv[qc + 3];
                const int qg = q0 + qc;
                float* dst = pout + (size_t)(k0 + kk) * Q_ + qg;
                if (qg + 3 < Q_) {
                    *reinterpret_cast<float4*>(dst) = w;
                } else {
                    if (qg     < Q_) dst[0] = w.x;
                    if (qg + 1 < Q_) dst[1] = w.y;
                    if (qg + 2 < Q_) dst[2] = w.z;
                    if (qg + 3 < Q_) dst[3] = w.w;
                }
            }
        }
        __syncthreads();
    }

    // epilogue: mem = U * inv[q]
#pragma unroll
    for (int mt = 0; mt < 2; ++mt)
#pragma unroll
        for (int nt = 0; nt < 3; ++nt)
#pragma unroll
            for (int j = 0; j < 4; ++j) {
                int r  = wm * 32 + mt * 16 + ((j & 2) ? (g + 8) : g);
                int cq = wn * 24 + nt * 8 + tg * 2 + (j & 1);
                int qg = q0 + cq;
                if (qg < Q_)
                    out_mem[((size_t)b * DO + do0 + r) * Q_ + qg] =
                        acc[mt][nt][j] * sinv[cq];
            }
}

extern "C" void kernel_launch(void* const* d_in, const int* in_sizes, int n_in,
                              void* d_out, int out_size) {
    const float* m_in  = (const float*)d_in[0];
    const float* m_out = (const float*)d_in[1];
    const float* q_in  = (const float*)d_in[2];
    const float* cst   = (const float*)d_in[3];
    float* out = (float*)d_out;

    cudaFuncSetAttribute(k1_scores, cudaFuncAttributeMaxDynamicSharedMemorySize,
                         K1SMEMF * 4);
    cudaFuncSetAttribute(k3_out, cudaFuncAttributeMaxDynamicSharedMemorySize,
                         SMEMF * 4);

    k1_scores<<<dim3(NKT, NQT, B_), 256, K1SMEMF * 4>>>(m_in, q_in);
    k2_inv<<<(B_ * QPAD + 255) / 256, 256>>>(cst);
    k3_out<<<dim3(8, NQT, B_), 256, SMEMF * 4>>>(m_out, out, out + MEM_ELEMS);
}